// round 8
// baseline (speedup 1.0000x reference)
#include <cuda_runtime.h>
#include <math.h>

#define FULLMASK 0xffffffffu
#define NS   25
#define NF   216
#define TLEN 2048

// dynamic smem layout (bytes)
#define OFF_B     0
#define OFF_FLAT  27648              // 216*32*4
#define OFF_A     (27648 + 32768)    // + 8*2048*2
#define OFF_I     (OFF_A + 2500)
#define OFF_RED   (OFF_I + 128)
#define SMEM_TOTAL (OFF_RED + 512)

// ---------------- constant tables ----------------
__constant__ __align__(16) int c_srcTab[32 * 4] = {
    0,0,0,0,     0,1,1,1,     1,2,2,2,     2,3,3,3,
    3,16,4,4,    4,5,5,5,     5,6,6,6,     6,19,3,7,
    7,8,8,8,     8,9,9,9,     9,22,3,6,    10,11,11,11,
    11,12,12,12, 12,13,13,13, 3,16,14,14,  14,15,15,15,
    15,16,16,16, 6,19,17,17,  17,18,18,18, 18,19,19,19,
    9,22,20,20,  20,21,21,21, 21,22,22,22, 13,23,23,23,
    23,24,24,24, 25,25,25,25, 26,26,26,26, 27,27,27,27,
    28,28,28,28, 29,29,29,29, 30,30,30,30, 31,31,31,31
};
__constant__ int c_deg[32] = {1,1,1,1,2,1,1,3,1,1,4,1,1,2,2,1,1,2,1,1,2,1,1,2,2,0,0,0,0,0,0,0};

__constant__ int c_pred[25][4] = {
    {0,0,0,0},{0,0,0,0},{1,0,0,0},{2,0,0,0},{3,16,0,0},{4,0,0,0},{5,0,0,0},
    {6,19,3,0},{7,0,0,0},{8,0,0,0},{9,22,3,6},{10,0,0,0},{11,0,0,0},{12,13,0,0},
    {3,16,0,0},{14,0,0,0},{15,0,0,0},{6,19,0,0},{17,0,0,0},{18,0,0,0},
    {9,22,0,0},{20,0,0,0},{21,0,0,0},{13,23,0,0},{23,24,0,0}
};
__constant__ int c_pcnt[25] = {1,1,1,1,2,1,1,3,1,1,4,1,1,2,2,1,1,2,1,1,2,1,1,2,2};

__constant__ int c_adds[29][7] = {
    { 0, 10,10,10, 0,1,    0},
    { 1, 10,10, 0, 0,1,   84},
    { 2, 10, 0, 3, 0,1,  105},
    { 3,  0, 3, 2, 0,0,    0},
    { 4,  3, 2,10, 0,1,  111},
    { 5,  2,10,10, 0,1,  123},
    { 6, 10,10,10, 0,1,  159},
    { 7, 10,10,10, 0,1,  243},
    { 8, 10,10,10, 0,1,  327},
    { 9, 10,10,10, 0,1,  411},
    {10, 10,10, 3, 2,1,  495},
    {11, 10, 3, 0, 2,1,  511},
    {11, 10, 3, 2, 2,1,  515},
    {12,  3, 0, 0, 2,0,    0},
    {12,  3, 0, 2, 2,0,    0},
    {12,  3, 2, 0, 2,0,    0},
    {13, 10,10,10, 2,1,  519},
    {14, 10,10,10, 0,1,  583},
    {15, 10,10,10, 0,1,  667},
    {16, 10,10,10, 0,1,  751},
    {17, 10,10,10, 0,1,  835},
    {18, 10,10,10, 0,1,  919},
    {19, 10,10,10, 0,1, 1003},
    {20, 10,10,10, 0,1, 1087},
    {21, 10,10,10, 0,1, 1171},
    {22, 10,10,10, 0,1, 1255},
    {23, 10,10, 5, 2,1, 1339},
    {23, 10, 5, 5, 2,1, 1355},
    {24,  5, 5, 5, 2,0,    0}
};

// ---------------- helpers ----------------
__device__ __forceinline__ int codeList(int ch, int* o) {
    if (ch == 10) { o[0]=0; o[1]=1; o[2]=2; o[3]=3; return 4; }
    o[0] = ch; return 1;
}

__device__ void addB(float* shB, const float* w,
                     int state, int e0, int e1, int e2,
                     int xp, int trainable, int k)
{
    int a0[6], a1[6], a2[6];
    int n0 = codeList(e0, a0);
    int n1 = codeList(e1, a1);
    int n2 = codeList(e2, a2);
    if (xp == 0) { a0[n0++] = 4; a1[n1++] = 4; }
    int t = 0;
    for (int i0 = 0; i0 < n0; i0++) { int c0 = a0[i0];
        for (int i1 = 0; i1 < n1; i1++) { int c1 = a1[i1];
            if (c0 != 4 && c1 == 4) continue;
            for (int i2 = 0; i2 < n2; i2++) { int c2 = a2[i2];
                shB[((c0*36 + c1*6 + c2) << 5) + state] = trainable ? w[k + t] : 1.0f;
                t++;
            }
        }
    }
}

// ---------------- fused kernel: 2 rows per warp ----------------
__global__ __launch_bounds__(128, 1)
void hmm_fused(const float* __restrict__ tw,
               const float* __restrict__ ew,
               const float* __restrict__ iw,
               const int* __restrict__ tokens,
               float* __restrict__ out, int rows)
{
    extern __shared__ char dyn[];
    float* shB   = (float*)(dyn + OFF_B);     // [flat][state(32)]
    short* sFlat = (short*)(dyn + OFF_FLAT);  // 8 rows x 2048
    float* sA    = (float*)(dyn + OFF_A);
    float* sI    = (float*)(dyn + OFF_I);
    float* sRed  = (float*)(dyn + OFF_RED);
    const int tid = threadIdx.x;

    // ---- init ----
    for (int i = tid; i < NF*32; i += 128) shB[i] = ((i & 31) < 25) ? -1e30f : 0.0f;
    for (int i = tid; i < 25*25;  i += 128) sA[i] = -1e30f;
    __syncthreads();

    // ---- B logits ----
    if (tid < 29) {
        const int* d = c_adds[tid];
        addB(shB, ew, d[0], d[1], d[2], d[3], d[4], d[5], d[6]);
    }
    // ---- A logits ----
    if (tid == 32) {
        float w0=tw[0],w1=tw[1],w2=tw[2],w3=tw[3],w4=tw[4];
        float w5=tw[5],w6=tw[6],w7=tw[7],w8=tw[8],w9=tw[9];
        sA[0*25+0]=1.f-w0; sA[0*25+1]=w0;
        sA[1*25+2]=1.f;    sA[2*25+3]=1.f;
        sA[3*25+4]=w1;     sA[6*25+7]=w2;
        sA[4*25+5]=1.f;    sA[7*25+8]=1.f;
        sA[5*25+6]=1.f;    sA[8*25+9]=1.f;
        sA[3*25+14]=w3;    sA[6*25+17]=w4;   sA[9*25+20]=w5;
        sA[9*25+10]=1.f-w5;
        sA[14*25+15]=1.f;  sA[17*25+18]=1.f; sA[20*25+21]=1.f;
        sA[15*25+16]=1.f;  sA[18*25+19]=1.f; sA[21*25+22]=1.f;
        sA[16*25+4]=w6;    sA[19*25+7]=w7;   sA[22*25+10]=w8;
        sA[16*25+14]=1.f-w6; sA[19*25+17]=1.f-w7; sA[22*25+20]=1.f-w8;
        sA[3*25+7]=1.f - w9*w9;
        sA[3*25+10]=1.f - w9*w9*w9;
        sA[6*25+10]=1.f - w9*w9;
        sA[10*25+11]=1.f; sA[11*25+12]=1.f; sA[12*25+13]=1.f;
        sA[13*25+13]=1.f; sA[13*25+23]=1.f;
        sA[23*25+23]=1.f; sA[23*25+24]=1.f; sA[24*25+24]=1.f;
    }
    // ---- I softmax ----
    if (tid == 64) {
        float mx = -1e30f;
        for (int i = 0; i < 9; i++) mx = fmaxf(mx, iw[i]);
        float v[9], sum = 0.f;
        for (int i = 0; i < 9; i++) { v[i] = expf(iw[i]-mx); sum += v[i]; }
        for (int i = 0; i < 9; i++) sI[i] = v[i] / sum;
        for (int i = 9; i < 32; i++) sI[i] = 0.f;
    }

    // ---- per-warp: precompute flat contexts for its 2 rows ----
    const int lane = tid & 31;
    const int wq   = tid >> 5;
    const int rowA = blockIdx.x * 8 + wq * 2;
    const int rowB = rowA + 1;
    for (int r = 0; r < 2; r++) {
        int row = rowA + r;
        if (row >= rows) break;
        short* myFlat = sFlat + (wq*2 + r) * TLEN;
        const int* tok = tokens + (size_t)row * TLEN;
        int c1 = 4, c2 = 4;
        for (int t0 = 0; t0 < TLEN; t0 += 32) {
            int tcv = tok[t0 + lane];
            int t1v = __shfl_up_sync(FULLMASK, tcv, 1);
            int t2v = __shfl_up_sync(FULLMASK, tcv, 2);
            if (lane == 0) { t1v = c1; t2v = c2; }
            if (lane == 1) { t2v = c1; }
            myFlat[t0 + lane] = (short)(t2v*36 + t1v*6 + tcv);
            c2 = __shfl_sync(FULLMASK, tcv, 30);
            c1 = __shfl_sync(FULLMASK, tcv, 31);
        }
    }
    __syncthreads();

    // ---- A row softmax ----
    if (tid < 25) {
        float mx = -1e30f;
        for (int j = 0; j < 25; j++) mx = fmaxf(mx, sA[tid*25+j]);
        float s = 0.f;
        for (int j = 0; j < 25; j++) { float v = expf(sA[tid*25+j]-mx); sA[tid*25+j]=v; s+=v; }
        float inv = 1.f / s;
        for (int j = 0; j < 25; j++) sA[tid*25+j] *= inv;
    }
    // ---- B column softmax, 4-way parallel per state ----
    {
        const int s  = tid & 31;
        const int ch = tid >> 5;
        const int f0 = ch * 54, f1 = f0 + 54;
        float mx = -1e30f;
        for (int f = f0; f < f1; f++) mx = fmaxf(mx, shB[(f<<5)+s]);
        sRed[ch*32 + s] = mx;
        __syncthreads();
        mx = fmaxf(fmaxf(sRed[s], sRed[32+s]), fmaxf(sRed[64+s], sRed[96+s]));
        float sum = 0.f;
        for (int f = f0; f < f1; f++) {
            float v = __expf(shB[(f<<5)+s] - mx);
            shB[(f<<5)+s] = v; sum += v;
        }
        __syncthreads();
        sRed[ch*32 + s] = sum;
        __syncthreads();
        float tot = (sRed[s] + sRed[32+s]) + (sRed[64+s] + sRed[96+s]);
        float inv = 1.f / tot;
        for (int f = f0; f < f1; f++) shB[(f<<5)+s] *= inv;
    }
    __syncthreads();

    // ---- per-lane constants (shared across both rows) ----
    int   ps[4] = {0,0,0,0};
    int   pk[4]; pk[0]=0; pk[1]=0; pk[2]=0; pk[3]=0;
    float pc[4] = {0.f,0.f,0.f,0.f};
    if (lane < 25) {
        int cnt = 0;
        for (int ki = 0; ki < c_pcnt[lane]; ki++) {
            int k = c_pred[lane][ki];
            float akj = sA[k*25 + lane];
            for (int ii = 0; ii < c_pcnt[k]; ii++) {
                int i = c_pred[k][ii];
                ps[cnt] = i; pk[cnt] = k;
                pc[cnt] = sA[i*25 + k] * akj * 32768.0f;   // fold 2^15 (exact)
                cnt++;
            }
        }
    }
    const int   S0 = ps[0], S1 = ps[1], S2 = ps[2], S3 = ps[3];
    const int   K0 = pk[0], K1 = pk[1], K2 = pk[2], K3 = pk[3];
    const float C0 = pc[0], C1 = pc[1], C2 = pc[2], C3 = pc[3];

    const int u0 = c_srcTab[lane*4+0], u1 = c_srcTab[lane*4+1];
    const int u2 = c_srcTab[lane*4+2], u3 = c_srcTab[lane*4+3];
    const int dg = c_deg[lane];
    float v0 = (lane < 25 && dg > 0) ? sA[u0*25 + lane] : 0.f;
    float v1 = (lane < 25 && dg > 1) ? sA[u1*25 + lane] : 0.f;
    float v2 = (lane < 25 && dg > 2) ? sA[u2*25 + lane] : 0.f;
    float v3 = (lane < 25 && dg > 3) ? sA[u3*25 + lane] : 0.f;

    if (rowA >= rows) return;
    const bool haveB = (rowB < rows);
    short* flA = sFlat + (wq*2 + 0) * TLEN;
    short* flB = haveB ? (sFlat + (wq*2 + 1) * TLEN) : flA;

    // ---- t=0 and t=1 per row ----
    float a0, a1;
    int expsum0 = 0, expsum1 = 0;
    {
        a0 = sI[lane] * shB[((int)flA[0] << 5) + lane];
        float e = shB[((int)flA[1] << 5) + lane];
        float x0 = __shfl_sync(FULLMASK, a0, u0);
        float x1 = __shfl_sync(FULLMASK, a0, u1);
        float x2 = __shfl_sync(FULLMASK, a0, u2);
        float x3 = __shfl_sync(FULLMASK, a0, u3);
        a0 = (fmaf(x0, v0, x1*v1) + fmaf(x2, v2, x3*v3)) * e;
    }
    {
        a1 = sI[lane] * shB[((int)flB[0] << 5) + lane];
        float e = shB[((int)flB[1] << 5) + lane];
        float x0 = __shfl_sync(FULLMASK, a1, u0);
        float x1 = __shfl_sync(FULLMASK, a1, u1);
        float x2 = __shfl_sync(FULLMASK, a1, u2);
        float x3 = __shfl_sync(FULLMASK, a1, u3);
        a1 = (fmaf(x0, v0, x1*v1) + fmaf(x2, v2, x3*v3)) * e;
    }

    float sc0 = 1.f, sc1 = 1.f; int pend0 = 0, pend1 = 0;
    const short2* fpA = (const short2*)flA;
    const short2* fpB = (const short2*)flB;

    // ---- head: pairs 1..7, both rows interleaved ----
#define PAIR2(P, MODE)                                                        \
    {                                                                         \
        short2 fa = fpA[(P)];                                                 \
        short2 fb = fpB[(P)];                                                 \
        int foA = (int)fa.x << 5, foB = (int)fb.x << 5;                       \
        float eA = shB[((int)fa.y << 5) + lane];                              \
        float eB = shB[((int)fb.y << 5) + lane];                              \
        float wA0 = C0*shB[foA+K0]*eA, wA1 = C1*shB[foA+K1]*eA;               \
        float wA2 = C2*shB[foA+K2]*eA, wA3 = C3*shB[foA+K3]*eA;               \
        float wB0 = C0*shB[foB+K0]*eB, wB1 = C1*shB[foB+K1]*eB;               \
        float wB2 = C2*shB[foB+K2]*eB, wB3 = C3*shB[foB+K3]*eB;               \
        float xa0 = __shfl_sync(FULLMASK, a0, S0);                            \
        float xa1 = __shfl_sync(FULLMASK, a0, S1);                            \
        float xa2 = __shfl_sync(FULLMASK, a0, S2);                            \
        float xa3 = __shfl_sync(FULLMASK, a0, S3);                            \
        float xb0 = __shfl_sync(FULLMASK, a1, S0);                            \
        float xb1 = __shfl_sync(FULLMASK, a1, S1);                            \
        float xb2 = __shfl_sync(FULLMASK, a1, S2);                            \
        float xb3 = __shfl_sync(FULLMASK, a1, S3);                            \
        a0 = fmaf(xa1, wA1, xa0*wA0) + fmaf(xa3, wA3, xa2*wA2);               \
        a1 = fmaf(xb1, wB1, xb0*wB0) + fmaf(xb3, wB3, xb2*wB2);               \
        if ((MODE) == 1) {                                                    \
            int m0 = __reduce_max_sync(FULLMASK, (__float_as_int(a0) >> 23) & 255); \
            int m1 = __reduce_max_sync(FULLMASK, (__float_as_int(a1) >> 23) & 255); \
            sc0 = __int_as_float((254 - m0) << 23); pend0 = m0 - 127;         \
            sc1 = __int_as_float((254 - m1) << 23); pend1 = m1 - 127;         \
        }                                                                     \
        if ((MODE) == 2) { a0 *= sc0; expsum0 += pend0;                       \
                           a1 *= sc1; expsum1 += pend1; }                     \
    }

    PAIR2(1,0) PAIR2(2,0) PAIR2(3,0) PAIR2(4,0) PAIR2(5,1) PAIR2(6,0) PAIR2(7,2)
#undef PAIR2

    // ---- main: 127 blocks of 8 pairs, both rows ----
    int4 fA0 = *(const int4*)(flA + 16);
    int4 fA1 = *(const int4*)(flA + 24);
    int4 fB0 = *(const int4*)(flB + 16);
    int4 fB1 = *(const int4*)(flB + 24);

#define STAGE2(i)                                                             \
    {                                                                         \
        int kA_ = ccA[(i)], kB_ = ccB[(i)];                                   \
        float eA_ = shB[(((int)((unsigned)kA_ >> 16)) << 5) + lane];          \
        float eB_ = shB[(((int)((unsigned)kB_ >> 16)) << 5) + lane];          \
        int fA_ = (kA_ & 0xffff) << 5;                                        \
        int fB_ = (kB_ & 0xffff) << 5;                                        \
        WA[(i)][0] = C0 * shB[fA_ + K0] * eA_;                                \
        WA[(i)][1] = C1 * shB[fA_ + K1] * eA_;                                \
        WA[(i)][2] = C2 * shB[fA_ + K2] * eA_;                                \
        WA[(i)][3] = C3 * shB[fA_ + K3] * eA_;                                \
        WB[(i)][0] = C0 * shB[fB_ + K0] * eB_;                                \
        WB[(i)][1] = C1 * shB[fB_ + K1] * eB_;                                \
        WB[(i)][2] = C2 * shB[fB_ + K2] * eB_;                                \
        WB[(i)][3] = C3 * shB[fB_ + K3] * eB_;                                \
    }

    for (int pb = 8; pb <= 1016; pb += 8) {
        int ccA[8], ccB[8];
        ccA[0]=fA0.x; ccA[1]=fA0.y; ccA[2]=fA0.z; ccA[3]=fA0.w;
        ccA[4]=fA1.x; ccA[5]=fA1.y; ccA[6]=fA1.z; ccA[7]=fA1.w;
        ccB[0]=fB0.x; ccB[1]=fB0.y; ccB[2]=fB0.z; ccB[3]=fB0.w;
        ccB[4]=fB1.x; ccB[5]=fB1.y; ccB[6]=fB1.z; ccB[7]=fB1.w;
        if (pb < 1016) {
            fA0 = *(const int4*)(flA + 2*pb + 16);
            fA1 = *(const int4*)(flA + 2*pb + 24);
            fB0 = *(const int4*)(flB + 2*pb + 16);
            fB1 = *(const int4*)(flB + 2*pb + 24);
        }
        float WA[8][4], WB[8][4];
        STAGE2(0) STAGE2(1)
        #pragma unroll
        for (int i = 0; i < 8; i++) {
            if (i < 6) STAGE2(i+2)
            float xa0 = __shfl_sync(FULLMASK, a0, S0);
            float xa1 = __shfl_sync(FULLMASK, a0, S1);
            float xa2 = __shfl_sync(FULLMASK, a0, S2);
            float xa3 = __shfl_sync(FULLMASK, a0, S3);
            float xb0 = __shfl_sync(FULLMASK, a1, S0);
            float xb1 = __shfl_sync(FULLMASK, a1, S1);
            float xb2 = __shfl_sync(FULLMASK, a1, S2);
            float xb3 = __shfl_sync(FULLMASK, a1, S3);
            a0 = fmaf(xa1, WA[i][1], xa0*WA[i][0]) + fmaf(xa3, WA[i][3], xa2*WA[i][2]);
            a1 = fmaf(xb1, WB[i][1], xb0*WB[i][0]) + fmaf(xb3, WB[i][3], xb2*WB[i][2]);
            if (i == 5) {
                int m0 = __reduce_max_sync(FULLMASK, (__float_as_int(a0) >> 23) & 255);
                int m1 = __reduce_max_sync(FULLMASK, (__float_as_int(a1) >> 23) & 255);
                sc0 = __int_as_float((254 - m0) << 23); pend0 = m0 - 127;
                sc1 = __int_as_float((254 - m1) << 23); pend1 = m1 - 127;
            }
            if (i == 7) {
                a0 *= sc0; expsum0 += pend0;
                a1 *= sc1; expsum1 += pend1;
            }
        }
    }
#undef STAGE2

    // ---- final: ll = log(sum alpha) + (expsum - 15*1023) * ln2 ----
    float s0 = a0, s1 = a1;
    #pragma unroll
    for (int o = 16; o; o >>= 1) {
        s0 += __shfl_xor_sync(FULLMASK, s0, o);
        s1 += __shfl_xor_sync(FULLMASK, s1, o);
    }
    if (lane == 0) {
        out[rowA] = logf(s0) + 0.6931471805599453f * (float)(expsum0 - 15345);
        if (haveB)
            out[rowB] = logf(s1) + 0.6931471805599453f * (float)(expsum1 - 15345);
    }
}

// ---------------- entry point ----------------
extern "C" void kernel_launch(void* const* d_in, const int* in_sizes, int n_in,
                              void* d_out, int out_size)
{
    const float* tw     = (const float*)d_in[0];
    const float* ew     = (const float*)d_in[1];
    const float* iw     = (const float*)d_in[2];
    const int*   tokens = (const int*)  d_in[3];
    float*       out    = (float*)d_out;

    int rows = in_sizes[3] / TLEN;

    static bool attr_set = false;
    if (!attr_set) {
        cudaFuncSetAttribute(hmm_fused,
                             cudaFuncAttributeMaxDynamicSharedMemorySize,
                             SMEM_TOTAL);
        attr_set = true;
    }
    hmm_fused<<<(rows + 7) / 8, 128, SMEM_TOTAL>>>(tw, ew, iw, tokens, out, rows);
}

// round 9
// speedup vs baseline: 1.6248x; 1.6248x over previous
#include <cuda_runtime.h>
#include <math.h>

#define FULLMASK 0xffffffffu
#define NS   25
#define NF   216
#define TLEN 2048

// dynamic smem layout (bytes)
#define OFF_B     0                        // 216*32*4   = 27648
#define OFF_Q     27648                    // 216*32*16  = 110592
#define OFF_FLAT  (27648 + 110592)         // 4*2048*2   = 16384
#define OFF_A     (OFF_FLAT + 16384)       // 2500
#define OFF_I     (OFF_A + 2500)           // 128
#define OFF_RED   (OFF_I + 128)            // 512
#define SMEM_TOTAL (OFF_RED + 512)

// ---------------- constant tables ----------------
__constant__ __align__(16) int c_srcTab[32 * 4] = {
    0,0,0,0,     0,1,1,1,     1,2,2,2,     2,3,3,3,
    3,16,4,4,    4,5,5,5,     5,6,6,6,     6,19,3,7,
    7,8,8,8,     8,9,9,9,     9,22,3,6,    10,11,11,11,
    11,12,12,12, 12,13,13,13, 3,16,14,14,  14,15,15,15,
    15,16,16,16, 6,19,17,17,  17,18,18,18, 18,19,19,19,
    9,22,20,20,  20,21,21,21, 21,22,22,22, 13,23,23,23,
    23,24,24,24, 25,25,25,25, 26,26,26,26, 27,27,27,27,
    28,28,28,28, 29,29,29,29, 30,30,30,30, 31,31,31,31
};
__constant__ int c_deg[32] = {1,1,1,1,2,1,1,3,1,1,4,1,1,2,2,1,1,2,1,1,2,1,1,2,2,0,0,0,0,0,0,0};

__constant__ int c_pred[25][4] = {
    {0,0,0,0},{0,0,0,0},{1,0,0,0},{2,0,0,0},{3,16,0,0},{4,0,0,0},{5,0,0,0},
    {6,19,3,0},{7,0,0,0},{8,0,0,0},{9,22,3,6},{10,0,0,0},{11,0,0,0},{12,13,0,0},
    {3,16,0,0},{14,0,0,0},{15,0,0,0},{6,19,0,0},{17,0,0,0},{18,0,0,0},
    {9,22,0,0},{20,0,0,0},{21,0,0,0},{13,23,0,0},{23,24,0,0}
};
__constant__ int c_pcnt[25] = {1,1,1,1,2,1,1,3,1,1,4,1,1,2,2,1,1,2,1,1,2,1,1,2,2};

__constant__ int c_adds[29][7] = {
    { 0, 10,10,10, 0,1,    0},
    { 1, 10,10, 0, 0,1,   84},
    { 2, 10, 0, 3, 0,1,  105},
    { 3,  0, 3, 2, 0,0,    0},
    { 4,  3, 2,10, 0,1,  111},
    { 5,  2,10,10, 0,1,  123},
    { 6, 10,10,10, 0,1,  159},
    { 7, 10,10,10, 0,1,  243},
    { 8, 10,10,10, 0,1,  327},
    { 9, 10,10,10, 0,1,  411},
    {10, 10,10, 3, 2,1,  495},
    {11, 10, 3, 0, 2,1,  511},
    {11, 10, 3, 2, 2,1,  515},
    {12,  3, 0, 0, 2,0,    0},
    {12,  3, 0, 2, 2,0,    0},
    {12,  3, 2, 0, 2,0,    0},
    {13, 10,10,10, 2,1,  519},
    {14, 10,10,10, 0,1,  583},
    {15, 10,10,10, 0,1,  667},
    {16, 10,10,10, 0,1,  751},
    {17, 10,10,10, 0,1,  835},
    {18, 10,10,10, 0,1,  919},
    {19, 10,10,10, 0,1, 1003},
    {20, 10,10,10, 0,1, 1087},
    {21, 10,10,10, 0,1, 1171},
    {22, 10,10,10, 0,1, 1255},
    {23, 10,10, 5, 2,1, 1339},
    {23, 10, 5, 5, 2,1, 1355},
    {24,  5, 5, 5, 2,0,    0}
};

// ---------------- helpers ----------------
__device__ __forceinline__ int codeList(int ch, int* o) {
    if (ch == 10) { o[0]=0; o[1]=1; o[2]=2; o[3]=3; return 4; }
    o[0] = ch; return 1;
}

__device__ void addB(float* shB, const float* w,
                     int state, int e0, int e1, int e2,
                     int xp, int trainable, int k)
{
    int a0[6], a1[6], a2[6];
    int n0 = codeList(e0, a0);
    int n1 = codeList(e1, a1);
    int n2 = codeList(e2, a2);
    if (xp == 0) { a0[n0++] = 4; a1[n1++] = 4; }
    int t = 0;
    for (int i0 = 0; i0 < n0; i0++) { int c0 = a0[i0];
        for (int i1 = 0; i1 < n1; i1++) { int c1 = a1[i1];
            if (c0 != 4 && c1 == 4) continue;
            for (int i2 = 0; i2 < n2; i2++) { int c2 = a2[i2];
                shB[((c0*36 + c1*6 + c2) << 5) + state] = trainable ? w[k + t] : 1.0f;
                t++;
            }
        }
    }
}

// ---------------- fused kernel ----------------
__global__ __launch_bounds__(128, 1)
void hmm_fused(const float* __restrict__ tw,
               const float* __restrict__ ew,
               const float* __restrict__ iw,
               const int* __restrict__ tokens,
               float* __restrict__ out, int rows)
{
    extern __shared__ char dyn[];
    float*  shB   = (float*) (dyn + OFF_B);     // [flat][state(32)]
    float4* sQ    = (float4*)(dyn + OFF_Q);     // [flat][lane] -> 4 folded coeffs
    short*  sFlat = (short*) (dyn + OFF_FLAT);  // 4 rows x 2048
    float*  sA    = (float*) (dyn + OFF_A);
    float*  sI    = (float*) (dyn + OFF_I);
    float*  sRed  = (float*) (dyn + OFF_RED);
    const int tid = threadIdx.x;

    // ---- init ----
    for (int i = tid; i < NF*32; i += 128) shB[i] = ((i & 31) < 25) ? -1e30f : 0.0f;
    for (int i = tid; i < 25*25;  i += 128) sA[i] = -1e30f;
    __syncthreads();

    // ---- B logits (29 disjoint adds) ----
    if (tid < 29) {
        const int* d = c_adds[tid];
        addB(shB, ew, d[0], d[1], d[2], d[3], d[4], d[5], d[6]);
    }
    // ---- A logits ----
    if (tid == 32) {
        float w0=tw[0],w1=tw[1],w2=tw[2],w3=tw[3],w4=tw[4];
        float w5=tw[5],w6=tw[6],w7=tw[7],w8=tw[8],w9=tw[9];
        sA[0*25+0]=1.f-w0; sA[0*25+1]=w0;
        sA[1*25+2]=1.f;    sA[2*25+3]=1.f;
        sA[3*25+4]=w1;     sA[6*25+7]=w2;
        sA[4*25+5]=1.f;    sA[7*25+8]=1.f;
        sA[5*25+6]=1.f;    sA[8*25+9]=1.f;
        sA[3*25+14]=w3;    sA[6*25+17]=w4;   sA[9*25+20]=w5;
        sA[9*25+10]=1.f-w5;
        sA[14*25+15]=1.f;  sA[17*25+18]=1.f; sA[20*25+21]=1.f;
        sA[15*25+16]=1.f;  sA[18*25+19]=1.f; sA[21*25+22]=1.f;
        sA[16*25+4]=w6;    sA[19*25+7]=w7;   sA[22*25+10]=w8;
        sA[16*25+14]=1.f-w6; sA[19*25+17]=1.f-w7; sA[22*25+20]=1.f-w8;
        sA[3*25+7]=1.f - w9*w9;
        sA[3*25+10]=1.f - w9*w9*w9;
        sA[6*25+10]=1.f - w9*w9;
        sA[10*25+11]=1.f; sA[11*25+12]=1.f; sA[12*25+13]=1.f;
        sA[13*25+13]=1.f; sA[13*25+23]=1.f;
        sA[23*25+23]=1.f; sA[23*25+24]=1.f; sA[24*25+24]=1.f;
    }
    // ---- I softmax ----
    if (tid == 64) {
        float mx = -1e30f;
        for (int i = 0; i < 9; i++) mx = fmaxf(mx, iw[i]);
        float v[9], sum = 0.f;
        for (int i = 0; i < 9; i++) { v[i] = expf(iw[i]-mx); sum += v[i]; }
        for (int i = 0; i < 9; i++) sI[i] = v[i] / sum;
        for (int i = 9; i < 32; i++) sI[i] = 0.f;
    }

    // ---- per-warp: precompute flat contexts for own row ----
    const int lane = tid & 31;
    const int wq   = tid >> 5;
    const int row  = blockIdx.x * 4 + wq;
    short* myFlat = sFlat + wq * TLEN;
    const int* tok = tokens + (size_t)row * TLEN;
    if (row < rows) {
        int c1 = 4, c2 = 4;
        for (int t0 = 0; t0 < TLEN; t0 += 32) {
            int tcv = tok[t0 + lane];
            int t1v = __shfl_up_sync(FULLMASK, tcv, 1);
            int t2v = __shfl_up_sync(FULLMASK, tcv, 2);
            if (lane == 0) { t1v = c1; t2v = c2; }
            if (lane == 1) { t2v = c1; }
            myFlat[t0 + lane] = (short)(t2v*36 + t1v*6 + tcv);
            c2 = __shfl_sync(FULLMASK, tcv, 30);
            c1 = __shfl_sync(FULLMASK, tcv, 31);
        }
    }
    __syncthreads();

    // ---- A row softmax ----
    if (tid < 25) {
        float mx = -1e30f;
        for (int j = 0; j < 25; j++) mx = fmaxf(mx, sA[tid*25+j]);
        float s = 0.f;
        for (int j = 0; j < 25; j++) { float v = expf(sA[tid*25+j]-mx); sA[tid*25+j]=v; s+=v; }
        float inv = 1.f / s;
        for (int j = 0; j < 25; j++) sA[tid*25+j] *= inv;
    }
    // ---- B column softmax, 4-way parallel per state ----
    {
        const int s  = tid & 31;
        const int ch = tid >> 5;
        const int f0 = ch * 54, f1 = f0 + 54;
        float mx = -1e30f;
        for (int f = f0; f < f1; f++) mx = fmaxf(mx, shB[(f<<5)+s]);
        sRed[ch*32 + s] = mx;
        __syncthreads();
        mx = fmaxf(fmaxf(sRed[s], sRed[32+s]), fmaxf(sRed[64+s], sRed[96+s]));
        float sum = 0.f;
        for (int f = f0; f < f1; f++) {
            float v = __expf(shB[(f<<5)+s] - mx);
            shB[(f<<5)+s] = v; sum += v;
        }
        __syncthreads();
        sRed[ch*32 + s] = sum;
        __syncthreads();
        float tot = (sRed[s] + sRed[32+s]) + (sRed[64+s] + sRed[96+s]);
        float inv = 1.f / tot;
        for (int f = f0; f < f1; f++) shB[(f<<5)+s] *= inv;
    }
    __syncthreads();

    // ---- per-lane constants ----
    int   ps[4] = {0,0,0,0};
    int   pk[4]; pk[0]=0; pk[1]=0; pk[2]=0; pk[3]=0;
    float pc[4] = {0.f,0.f,0.f,0.f};
    if (lane < 25) {
        int cnt = 0;
        for (int ki = 0; ki < c_pcnt[lane]; ki++) {
            int k = c_pred[lane][ki];
            float akj = sA[k*25 + lane];
            for (int ii = 0; ii < c_pcnt[k]; ii++) {
                int i = c_pred[k][ii];
                ps[cnt] = i; pk[cnt] = k;
                pc[cnt] = sA[i*25 + k] * akj * 32768.0f;   // fold 2^15 (exact)
                cnt++;
            }
        }
    }
    const int   S0 = ps[0], S1 = ps[1], S2 = ps[2], S3 = ps[3];
    const int   K0 = pk[0], K1 = pk[1], K2 = pk[2], K3 = pk[3];
    const float C0 = pc[0], C1 = pc[1], C2 = pc[2], C3 = pc[3];

    // ---- build Q table: sQ[f][lane] = (C0*B[K0][f], ..., C3*B[K3][f]) ----
    // warp wq handles flats [wq*54, wq*54+54)
    {
        for (int f = wq * 54; f < wq * 54 + 54; f++) {
            int fo = f << 5;
            float4 q;
            q.x = C0 * shB[fo + K0];
            q.y = C1 * shB[fo + K1];
            q.z = C2 * shB[fo + K2];
            q.w = C3 * shB[fo + K3];
            sQ[fo + lane] = q;
        }
    }
    __syncthreads();

    // 1-step table (t=1)
    const int u0 = c_srcTab[lane*4+0], u1 = c_srcTab[lane*4+1];
    const int u2 = c_srcTab[lane*4+2], u3 = c_srcTab[lane*4+3];
    const int dg = c_deg[lane];
    float v0 = (lane < 25 && dg > 0) ? sA[u0*25 + lane] : 0.f;
    float v1 = (lane < 25 && dg > 1) ? sA[u1*25 + lane] : 0.f;
    float v2 = (lane < 25 && dg > 2) ? sA[u2*25 + lane] : 0.f;
    float v3 = (lane < 25 && dg > 3) ? sA[u3*25 + lane] : 0.f;

    if (row >= rows) return;

    // ---- t = 0 ----
    float a = sI[lane] * shB[((int)myFlat[0] << 5) + lane];

    // ---- t = 1: single 1-step ----
    {
        float e = shB[((int)myFlat[1] << 5) + lane];
        float x0 = __shfl_sync(FULLMASK, a, u0);
        float x1 = __shfl_sync(FULLMASK, a, u1);
        float x2 = __shfl_sync(FULLMASK, a, u2);
        float x3 = __shfl_sync(FULLMASK, a, u3);
        a = (fmaf(x0, v0, x1*v1) + fmaf(x2, v2, x3*v3)) * e;
    }
    int expsum = 0;
    float sc = 1.f; int pend = 0;

    const short2* fp = (const short2*)myFlat;

#define PAIRM(P, MODE)                                                        \
    {                                                                         \
        short2 ff = fp[(P)];                                                  \
        float4 q = sQ[((int)ff.x << 5) + lane];                               \
        float e1 = shB[((int)ff.y << 5) + lane];                              \
        float w0 = q.x * e1, w1 = q.y * e1, w2 = q.z * e1, w3 = q.w * e1;     \
        float x0 = __shfl_sync(FULLMASK, a, S0);                              \
        float x1 = __shfl_sync(FULLMASK, a, S1);                              \
        float x2 = __shfl_sync(FULLMASK, a, S2);                              \
        float x3 = __shfl_sync(FULLMASK, a, S3);                              \
        a = fmaf(x1, w1, x0*w0) + fmaf(x3, w3, x2*w2);                        \
        if ((MODE) == 1) {                                                    \
            int m = __reduce_max_sync(FULLMASK, (__float_as_int(a) >> 23) & 255); \
            sc = __int_as_float((254 - m) << 23);                             \
            pend = m - 127;                                                   \
        }                                                                     \
        if ((MODE) == 2) { a *= sc; expsum += pend; }                         \
    }

    // head: pairs 1..7 (measure at 5, apply at 7)
    PAIRM(1,0) PAIRM(2,0) PAIRM(3,0) PAIRM(4,0) PAIRM(5,1) PAIRM(6,0) PAIRM(7,2)
#undef PAIRM

    // ---- main: 127 blocks of 8 pairs, pairs 8..1023, flats double-buffered ----
    int4 fA = *(const int4*)(myFlat + 16);   // pairs 8..11
    int4 fB = *(const int4*)(myFlat + 24);   // pairs 12..15

#define STAGE(i)                                                              \
    {                                                                         \
        int k_ = cc[(i)];                                                     \
        float4 q_ = sQ[((k_ & 0xffff) << 5) + lane];                          \
        float e1_ = shB[(((int)((unsigned)k_ >> 16)) << 5) + lane];           \
        W[(i)][0] = q_.x * e1_;                                               \
        W[(i)][1] = q_.y * e1_;                                               \
        W[(i)][2] = q_.z * e1_;                                               \
        W[(i)][3] = q_.w * e1_;                                               \
    }

    for (int pb = 8; pb <= 1016; pb += 8) {
        int cc[8];
        cc[0]=fA.x; cc[1]=fA.y; cc[2]=fA.z; cc[3]=fA.w;
        cc[4]=fB.x; cc[5]=fB.y; cc[6]=fB.z; cc[7]=fB.w;
        if (pb < 1016) {
            fA = *(const int4*)(myFlat + 2*pb + 16);
            fB = *(const int4*)(myFlat + 2*pb + 24);
        }
        float W[8][4];
        STAGE(0) STAGE(1)
        #pragma unroll
        for (int i = 0; i < 8; i++) {
            if (i < 6) STAGE(i+2)
            float x0 = __shfl_sync(FULLMASK, a, S0);
            float x1 = __shfl_sync(FULLMASK, a, S1);
            float x2 = __shfl_sync(FULLMASK, a, S2);
            float x3 = __shfl_sync(FULLMASK, a, S3);
            a = fmaf(x1, W[i][1], x0*W[i][0]) + fmaf(x3, W[i][3], x2*W[i][2]);
            if (i == 5) {
                int m = __reduce_max_sync(FULLMASK, (__float_as_int(a) >> 23) & 255);
                sc = __int_as_float((254 - m) << 23);
                pend = m - 127;
            }
            if (i == 7) { a *= sc; expsum += pend; }
        }
    }
#undef STAGE

    // ---- final: ll = log(sum alpha) + (expsum - 15*1023) * ln2 ----
    float s = a;
    #pragma unroll
    for (int o = 16; o; o >>= 1) s += __shfl_xor_sync(FULLMASK, s, o);
    if (lane == 0)
        out[row] = logf(s) + 0.6931471805599453f * (float)(expsum - 15345);
}

// ---------------- entry point ----------------
extern "C" void kernel_launch(void* const* d_in, const int* in_sizes, int n_in,
                              void* d_out, int out_size)
{
    const float* tw     = (const float*)d_in[0];
    const float* ew     = (const float*)d_in[1];
    const float* iw     = (const float*)d_in[2];
    const int*   tokens = (const int*)  d_in[3];
    float*       out    = (float*)d_out;

    int rows = in_sizes[3] / TLEN;

    cudaFuncSetAttribute(hmm_fused,
                         cudaFuncAttributeMaxDynamicSharedMemorySize,
                         SMEM_TOTAL);
    hmm_fused<<<(rows + 3) / 4, 128, SMEM_TOTAL>>>(tw, ew, iw, tokens, out, rows);
}